// round 16
// baseline (speedup 1.0000x reference)
#include <cuda_runtime.h>
#include <cuda_fp16.h>
#include <cstdint>

#define T_SEQ   512
#define B_DIM   256
#define H_DIM   256
#define E_DIM   6
#define C_DIM   10
#define CLUSTER 4
#define G_COLS  8
#define NTHREADS 512
#define KC_N    16                  // 16 k-chunks of 16 -> K = 256 (h only)

// B: per column 136 words (stride ==8 mod 32 -> conflict-free paired LDS.64).
// Word layout: k-pair kp stored at word bw(kp) = (kp>>3)*8 + (kp&3)*2 + ((kp>>2)&1)
#define SHI_W   136
#define B_MAT   (G_COLS * SHI_W * 4)             // 4352 B
#define OFF_BH   0                               // 2 ping-pong buffers (8704)
#define OFF_XB   (2 * B_MAT)                     // 8704  : x staged [t][col] (16384)
#define OFF_PXT  (OFF_XB + T_SEQ * G_COLS * 4)   // 25088 : PXT [10][64][4] f32 (10240)
#define SMEM_BYTES (OFF_PXT + 10240 + 16)

__device__ __forceinline__ uint32_t smem_u32(const void* p) {
    return (uint32_t)__cvta_generic_to_shared(p);
}
__device__ __forceinline__ uint32_t mapa_rank(uint32_t addr, int r) {
    uint32_t ret;
    asm("mapa.shared::cluster.u32 %0, %1, %2;" : "=r"(ret) : "r"(addr), "r"(r));
    return ret;
}
__device__ __forceinline__ void st_cluster_u32(uint32_t addr, uint32_t v) {
    asm volatile("st.shared::cluster.u32 [%0], %1;" :: "r"(addr), "r"(v) : "memory");
}
__device__ __forceinline__ void cluster_sync_() {
    asm volatile("barrier.cluster.arrive.aligned;\n\tbarrier.cluster.wait.aligned;" ::: "memory");
}
#define CL_ARRIVE() asm volatile("barrier.cluster.arrive.aligned;" ::: "memory")
#define CL_WAIT()   asm volatile("barrier.cluster.wait.aligned;" ::: "memory")

__device__ __forceinline__ void mma16816h(float c[4], const uint32_t a[4],
                                          uint32_t b0, uint32_t b1) {
    asm volatile("mma.sync.aligned.m16n8k16.row.col.f32.f16.f16.f32 "
                 "{%0,%1,%2,%3}, {%4,%5,%6,%7}, {%8,%9}, {%0,%1,%2,%3};"
                 : "+f"(c[0]), "+f"(c[1]), "+f"(c[2]), "+f"(c[3])
                 : "r"(a[0]), "r"(a[1]), "r"(a[2]), "r"(a[3]), "r"(b0), "r"(b1));
}
__device__ __forceinline__ uint32_t pack_h2(float a, float b) {
    __half2 t = __floats2half2_rn(a, b);
    return *(uint32_t*)&t;
}
__device__ __forceinline__ float tanhapx(float x) {
    float y;
    asm("tanh.approx.f32 %0, %1;" : "=f"(y) : "f"(x));
    return y;
}
__device__ __forceinline__ float sigapx(float x) {
    return fmaf(0.5f, tanhapx(0.5f * x), 0.5f);
}
__device__ __host__ __forceinline__ int bw_kp(int kp) {
    return ((kp >> 3) << 3) + ((kp & 3) << 1) + ((kp >> 2) & 1);
}

extern "C" __global__ void __launch_bounds__(NTHREADS, 1) __cluster_dims__(CLUSTER, 1, 1)
lstm_hmma_kernel(const int* __restrict__ x, const float* __restrict__ emb,
                 const float* __restrict__ Wxg, const float* __restrict__ Whg, const float* __restrict__ bg,
                 const float* __restrict__ Wxi, const float* __restrict__ Whi, const float* __restrict__ bi,
                 const float* __restrict__ Wxf, const float* __restrict__ Whf, const float* __restrict__ bf,
                 const float* __restrict__ Wxo, const float* __restrict__ Who, const float* __restrict__ bo,
                 const float* __restrict__ Wp,  const float* __restrict__ bp,
                 float* __restrict__ out)
{
    extern __shared__ char sb[];
    int*    xbuf = (int*)(sb + OFF_XB);
    float4* pxt  = (float4*)(sb + OFF_PXT);   // [v*64 + j] -> 4 gates
    const uint32_t sb32 = smem_u32(sb);

    const int tid  = threadIdx.x;
    const int wid  = tid >> 5;        // 0..15, one m16n8 tile per warp
    const int lane = tid & 31;
    const int g    = lane >> 2;       // groupID 0..7
    const int tg   = lane & 3;        // thread-in-group
    const int qa   = g >> 2;          // gate-pair selector
    const int rank = blockIdx.x & (CLUSTER - 1);
    const int cid  = blockIdx.x / CLUSTER;
    const int col0 = cid * G_COLS;

    const float* WhTab[4] = { Whg, Whi, Whf, Who };
    const float* WxTab[4] = { Wxg, Wxi, Wxf, Wxo };
    const float* bTab[4]  = { bg,  bi,  bf,  bo  };

    // ---- A fragments: Wh fp16, ROTATED chunk order ----
    // aHi[idx] holds k-chunk (4*rank + idx) & 15; idx 0..3 = this CTA's own chunks.
    // warp tile row r (0..15): gate = r>>2, j = 4*wid + (r&3)
    uint32_t aHi[KC_N][4];
    {
        auto getA = [&](int r, int k) -> float {
            int gate = r >> 2, j = 4 * wid + (r & 3);
            return WhTab[gate][(rank * 64 + j) * H_DIM + k];
        };
        const int ra = g, rb = g + 8;
        #pragma unroll
        for (int idx = 0; idx < KC_N; idx++) {
            const int kc = (4 * rank + idx) & 15;
            const int k0 = kc * 16 + 2 * tg;
            aHi[idx][0] = pack_h2(getA(ra, k0),     getA(ra, k0 + 1));
            aHi[idx][1] = pack_h2(getA(rb, k0),     getA(rb, k0 + 1));
            aHi[idx][2] = pack_h2(getA(ra, k0 + 8), getA(ra, k0 + 9));
            aHi[idx][3] = pack_h2(getA(rb, k0 + 8), getA(rb, k0 + 9));
        }
    }

    // thread-owned output mapping
    const int jloc = 4 * wid + (g & 3);          // 0..63
    const int cA   = 2 * tg + qa;                // owned column 0..7
    const int jlow = ((g & 1) == 0);
    const int kpl  = 2 * wid + ((g & 3) >> 1);   // j>>1, 0..31
    const uint32_t stCol = (uint32_t)((cA * SHI_W + bw_kp(rank * 32 + kpl)) * 4);

    // bias in registers for the owned column
    float biasA[4];
    #pragma unroll
    for (int q = 0; q < 4; q++) biasA[q] = bTab[q][col0 + cA];

    // ---- smem init: B zero, x staged, PXT table ----
    for (int i = tid; i < (2 * B_MAT) / 4; i += NTHREADS)
        ((uint32_t*)(sb + OFF_BH))[i] = 0u;
    for (int i = tid; i < G_COLS * T_SEQ; i += NTHREADS) {
        int c = i >> 9, t = i & 511;
        xbuf[t * G_COLS + c] = x[(col0 + c) * T_SEQ + t];
    }
    // PXT[v][j][q] = sum_e Wx[q][(rank*64+j), e] * emb[v, e]
    for (int i = tid; i < 10 * 64; i += NTHREADS) {
        int v = i >> 6, j = i & 63;
        const float* ev = emb + v * E_DIM;
        float4 r;
        float* rp = (float*)&r;
        #pragma unroll
        for (int q = 0; q < 4; q++) {
            const float* wx = WxTab[q] + (rank * 64 + j) * E_DIM;
            float s = 0.0f;
            #pragma unroll
            for (int e = 0; e < E_DIM; e++) s = fmaf(wx[e], ev[e], s);
            rp[q] = s;
        }
        pxt[i] = r;
    }

    // store targets: threadA -> {local STS, remote remA}; threadB -> {remB0, remB1}
    uint32_t remA, remB0, remB1;
    {
        uint32_t pr[CLUSTER];
        #pragma unroll
        for (int r = 0; r < CLUSTER; r++) pr[r] = mapa_rank(sb32, r);
        int rm[3], n = 0;
        #pragma unroll
        for (int r = 0; r < CLUSTER; r++) if (r != rank) rm[n++] = r;
        remA  = pr[rm[0]];
        remB0 = pr[rm[1]];
        remB1 = pr[rm[2]];
    }

    __syncthreads();
    cluster_sync_();
    CL_ARRIVE();                 // pairs with the wait at t=0

    const uint32_t coff = (uint32_t)(g * SHI_W * 4);
    float cst = 0.0f;

    int p = 0;
    for (int t = 0; t < T_SEQ; t++) {
        const char* Bp = sb + OFF_BH + p * B_MAT;

        // ---- phase 1 (pre-wait): own 4 chunks, locally produced ----
        float h0[4] = {0,0,0,0}, h1[4] = {0,0,0,0};
        float h2[4] = {0,0,0,0}, h3[4] = {0,0,0,0};
        #pragma unroll
        for (int idx = 0; idx < 4; idx++) {
            const int kc = (4 * rank + idx) & 15;
            uint2 A = *(const uint2*)(Bp + coff + (uint32_t)(kc * 8 + tg * 2) * 4);
            if (idx < 2) mma16816h(h0, aHi[idx], A.x, A.y);
            else         mma16816h(h1, aHi[idx], A.x, A.y);
        }

        // ---- preX: bias + PXT lookup (also pre-wait) ----
        int xi = xbuf[t * G_COLS + cA];
        float4 px4 = pxt[xi * 64 + jloc];

        CL_WAIT();               // peers' stores visible; buffer p^1 reads done

        // ---- phase 2: remaining 12 chunks across 4 chains ----
        #pragma unroll
        for (int idx = 4; idx < KC_N; idx++) {
            const int kc = (4 * rank + idx) & 15;
            uint2 A = *(const uint2*)(Bp + coff + (uint32_t)(kc * 8 + tg * 2) * 4);
            switch (idx & 3) {
                case 0: mma16816h(h0, aHi[idx], A.x, A.y); break;
                case 1: mma16816h(h1, aHi[idx], A.x, A.y); break;
                case 2: mma16816h(h2, aHi[idx], A.x, A.y); break;
                default: mma16816h(h3, aHi[idx], A.x, A.y); break;
            }
        }
        float d0 = (h0[0] + h1[0]) + (h2[0] + h3[0]);   // (gate qa,   col 2tg)
        float d1 = (h0[1] + h1[1]) + (h2[1] + h3[1]);   // (gate qa,   col 2tg+1)
        float d2 = (h0[2] + h1[2]) + (h2[2] + h3[2]);   // (gate qa+2, col 2tg)
        float d3 = (h0[3] + h1[3]) + (h2[3] + h3[3]);   // (gate qa+2, col 2tg+1)

        // ---- gate exchange with lane^16 (same j, other gate-pair) ----
        float sA = qa ? d0 : d1;
        float rA = __shfl_xor_sync(0xffffffffu, sA, 16);
        float sB = qa ? d2 : d3;
        float rB = __shfl_xor_sync(0xffffffffu, sB, 16);
        float pg0 = (qa ? rA : d0) + biasA[0] + px4.x;   // gate g
        float pg1 = (qa ? d1 : rA) + biasA[1] + px4.y;   // gate i
        float pg2 = (qa ? rB : d2) + biasA[2] + px4.z;   // gate f
        float pg3 = (qa ? d3 : rB) + biasA[3] + px4.w;   // gate o

        // ---- activations + c/h update for (jloc, cA) ----
        float gg = tanhapx(pg0), ii = sigapx(pg1), ff = sigapx(pg2), oo = sigapx(pg3);
        cst = fmaf(gg, ii, cst * ff);
        const float hv = tanhapx(cst) * oo;

        // ---- j-pair exchange with lane^4: (even j, odd j) same col ----
        float ov = __shfl_xor_sync(0xffffffffu, hv, 4);
        float va = jlow ? hv : ov;    // k even
        float vb = jlow ? ov : hv;    // k odd
        const uint32_t pkt = pack_h2(va, vb);

        // ---- stores into buffer p^1: threadA = local STS + 1 remote;
        //      threadB = 2 remotes (partner has identical pkt) ----
        const uint32_t dOff = (uint32_t)(OFF_BH + (p ^ 1) * B_MAT) + stCol;
        if (jlow) {
            *(uint32_t*)(sb + dOff) = pkt;          // own CTA, plain STS
            st_cluster_u32(remA + dOff, pkt);
        } else {
            st_cluster_u32(remB0 + dOff, pkt);
            st_cluster_u32(remB1 + dOff, pkt);
        }

        CL_ARRIVE();             // release remote stores; peers' wait at t+1
        __syncthreads();         // local STS visible for next step's phase 1
        p ^= 1;
    }

    CL_WAIT();                   // t=511 remote stores (into B[0]) visible

    // ---- projection: out[b, c] = sum_k Wp[c,k] h[k,b] + bp[c] (final h in B[0]) ----
    if (rank == 0 && tid < G_COLS * C_DIM) {
        const int col = tid / C_DIM;
        const int cls = tid % C_DIM;
        const uint32_t* Bc = (const uint32_t*)(sb + OFF_BH) + col * SHI_W;
        const float* wpr = Wp + cls * H_DIM;
        float s = bp[cls];
        for (int kp = 0; kp < H_DIM / 2; kp++) {
            uint32_t w = Bc[bw_kp(kp)];
            __half2 hw = *(__half2*)&w;
            s = fmaf(wpr[2 * kp],     __half2float(hw.x),
                fmaf(wpr[2 * kp + 1], __half2float(hw.y), s));
        }
        out[(col0 + col) * C_DIM + cls] = s;
    }
}

extern "C" void kernel_launch(void* const* d_in, const int* in_sizes, int n_in,
                              void* d_out, int out_size) {
    (void)in_sizes; (void)n_in; (void)out_size;
    const int*   x   = (const int*)  d_in[0];
    const float* emb = (const float*)d_in[1];
    const float* Wxg = (const float*)d_in[2];
    const float* Whg = (const float*)d_in[3];
    const float* bg  = (const float*)d_in[4];
    const float* Wxi = (const float*)d_in[5];
    const float* Whi = (const float*)d_in[6];
    const float* bi  = (const float*)d_in[7];
    const float* Wxf = (const float*)d_in[8];
    const float* Whf = (const float*)d_in[9];
    const float* bf  = (const float*)d_in[10];
    const float* Wxo = (const float*)d_in[11];
    const float* Who = (const float*)d_in[12];
    const float* bo  = (const float*)d_in[13];
    const float* Wp  = (const float*)d_in[14];
    const float* bp  = (const float*)d_in[15];
    float* out = (float*)d_out;

    cudaFuncSetAttribute(lstm_hmma_kernel,
                         cudaFuncAttributeMaxDynamicSharedMemorySize, SMEM_BYTES);
    // 32 clusters of 4 CTAs = 128 CTAs
    lstm_hmma_kernel<<<(B_DIM / G_COLS) * CLUSTER, NTHREADS, SMEM_BYTES>>>(
        x, emb, Wxg, Whg, bg, Wxi, Whi, bi, Wxf, Whf, bf, Wxo, Who, bo, Wp, bp, out);
}

// round 17
// speedup vs baseline: 1.1231x; 1.1231x over previous
#include <cuda_runtime.h>
#include <cuda_fp16.h>
#include <cstdint>

#define T_SEQ   512
#define B_DIM   256
#define H_DIM   256
#define E_DIM   6
#define C_DIM   10
#define CLUSTER 4
#define G_COLS  8
#define NTHREADS 512
#define KC_N    16                  // 16 k-chunks of 16 -> K = 256 (h only)

// B: per column 136 words (stride ==8 mod 32 -> conflict-free paired LDS.64).
// Word layout: k-pair kp stored at word bw(kp) = (kp>>3)*8 + (kp&3)*2 + ((kp>>2)&1)
#define SHI_W   136
#define B_MAT   (G_COLS * SHI_W * 4)             // 4352 B
#define OFF_BH   0                               // 2 ping-pong buffers (8704)
#define OFF_XB   (2 * B_MAT)                     // 8704  : x staged [t][col] (16384)
#define OFF_PXT  (OFF_XB + T_SEQ * G_COLS * 4)   // 25088 : PXT [10][64][4] f32 (10240)
#define OFF_MB   (OFF_PXT + 10240)               // 35328 : mbar [2]
#define SMEM_BYTES (OFF_MB + 16 + 16)
#define MB_COUNT 4u                 // 1 arrive per CTA per phase x 4 CTAs

__device__ __forceinline__ uint32_t smem_u32(const void* p) {
    return (uint32_t)__cvta_generic_to_shared(p);
}
__device__ __forceinline__ uint32_t mapa_rank(uint32_t addr, int r) {
    uint32_t ret;
    asm("mapa.shared::cluster.u32 %0, %1, %2;" : "=r"(ret) : "r"(addr), "r"(r));
    return ret;
}
__device__ __forceinline__ void st_cluster_u32(uint32_t addr, uint32_t v) {
    asm volatile("st.shared::cluster.u32 [%0], %1;" :: "r"(addr), "r"(v) : "memory");
}
__device__ __forceinline__ void cluster_sync_() {
    asm volatile("barrier.cluster.arrive.aligned;\n\tbarrier.cluster.wait.aligned;" ::: "memory");
}
__device__ __forceinline__ void mbar_init(uint32_t addr, uint32_t cnt) {
    asm volatile("mbarrier.init.shared.b64 [%0], %1;" :: "r"(addr), "r"(cnt) : "memory");
}
__device__ __forceinline__ void mbar_arrive_cluster(uint32_t addr) {
    asm volatile("mbarrier.arrive.release.cluster.shared::cluster.b64 _, [%0];"
                 :: "r"(addr) : "memory");
}
__device__ __forceinline__ void mbar_wait(uint32_t addr, uint32_t parity) {
    asm volatile("{\n\t.reg .pred P;\n\tWL_%=:\n\t"
                 "mbarrier.try_wait.parity.acquire.cluster.shared::cta.b64 P, [%0], %1, 0x989680;\n\t"
                 "@!P bra WL_%=;\n\t}" :: "r"(addr), "r"(parity) : "memory");
}
__device__ __forceinline__ void mma16816h(float c[4], const uint32_t a[4],
                                          uint32_t b0, uint32_t b1) {
    asm volatile("mma.sync.aligned.m16n8k16.row.col.f32.f16.f16.f32 "
                 "{%0,%1,%2,%3}, {%4,%5,%6,%7}, {%8,%9}, {%0,%1,%2,%3};"
                 : "+f"(c[0]), "+f"(c[1]), "+f"(c[2]), "+f"(c[3])
                 : "r"(a[0]), "r"(a[1]), "r"(a[2]), "r"(a[3]), "r"(b0), "r"(b1));
}
__device__ __forceinline__ uint32_t pack_h2(float a, float b) {
    __half2 t = __floats2half2_rn(a, b);
    return *(uint32_t*)&t;
}
__device__ __forceinline__ float tanhapx(float x) {
    float y;
    asm("tanh.approx.f32 %0, %1;" : "=f"(y) : "f"(x));
    return y;
}
__device__ __forceinline__ float sigapx(float x) {
    return fmaf(0.5f, tanhapx(0.5f * x), 0.5f);
}
__device__ __host__ __forceinline__ int bw_kp(int kp) {
    return ((kp >> 3) << 3) + ((kp & 3) << 1) + ((kp >> 2) & 1);
}

extern "C" __global__ void __launch_bounds__(NTHREADS, 1) __cluster_dims__(CLUSTER, 1, 1)
lstm_hmma_kernel(const int* __restrict__ x, const float* __restrict__ emb,
                 const float* __restrict__ Wxg, const float* __restrict__ Whg, const float* __restrict__ bg,
                 const float* __restrict__ Wxi, const float* __restrict__ Whi, const float* __restrict__ bi,
                 const float* __restrict__ Wxf, const float* __restrict__ Whf, const float* __restrict__ bf,
                 const float* __restrict__ Wxo, const float* __restrict__ Who, const float* __restrict__ bo,
                 const float* __restrict__ Wp,  const float* __restrict__ bp,
                 float* __restrict__ out)
{
    extern __shared__ char sb[];
    int*    xbuf = (int*)(sb + OFF_XB);
    float4* pxt  = (float4*)(sb + OFF_PXT);   // [v*64 + j] -> 4 gates
    const uint32_t sb32 = smem_u32(sb);

    const int tid  = threadIdx.x;
    const int wid  = tid >> 5;        // 0..15, one m16n8 tile per warp
    const int lane = tid & 31;
    const int g    = lane >> 2;       // groupID 0..7
    const int tg   = lane & 3;        // thread-in-group
    const int qa   = g >> 2;          // gate-pair selector
    const int rank = blockIdx.x & (CLUSTER - 1);
    const int cid  = blockIdx.x / CLUSTER;
    const int col0 = cid * G_COLS;

    const float* WhTab[4] = { Whg, Whi, Whf, Who };
    const float* WxTab[4] = { Wxg, Wxi, Wxf, Wxo };
    const float* bTab[4]  = { bg,  bi,  bf,  bo  };

    // ---- A fragments: Wh fp16, ROTATED chunk order ----
    // aHi[idx] = k-chunk (4*rank + idx) & 15; idx 0..3 are this CTA's own chunks.
    uint32_t aHi[KC_N][4];
    {
        auto getA = [&](int r, int k) -> float {
            int gate = r >> 2, j = 4 * wid + (r & 3);
            return WhTab[gate][(rank * 64 + j) * H_DIM + k];
        };
        const int ra = g, rb = g + 8;
        #pragma unroll
        for (int idx = 0; idx < KC_N; idx++) {
            const int kc = (4 * rank + idx) & 15;
            const int k0 = kc * 16 + 2 * tg;
            aHi[idx][0] = pack_h2(getA(ra, k0),     getA(ra, k0 + 1));
            aHi[idx][1] = pack_h2(getA(rb, k0),     getA(rb, k0 + 1));
            aHi[idx][2] = pack_h2(getA(ra, k0 + 8), getA(ra, k0 + 9));
            aHi[idx][3] = pack_h2(getA(rb, k0 + 8), getA(rb, k0 + 9));
        }
    }

    // thread-owned output mapping (j = 4*wid + (g&3))
    const int jloc = 4 * wid + (g & 3);          // 0..63
    const int cA   = 2 * tg + qa;                // owned column 0..7
    const int jlow = ((g & 1) == 0);
    const int kpl  = 2 * wid + ((g & 3) >> 1);   // j>>1, 0..31
    const uint32_t stCol = (uint32_t)((cA * SHI_W + bw_kp(rank * 32 + kpl)) * 4);

    // bias in registers for the owned column
    float biasA[4];
    #pragma unroll
    for (int q = 0; q < 4; q++) biasA[q] = bTab[q][col0 + cA];

    // ---- smem init: B zero, x staged, PXT table, mbarriers ----
    for (int i = tid; i < (2 * B_MAT) / 4; i += NTHREADS)
        ((uint32_t*)(sb + OFF_BH))[i] = 0u;
    for (int i = tid; i < G_COLS * T_SEQ; i += NTHREADS) {
        int c = i >> 9, t = i & 511;
        xbuf[t * G_COLS + c] = x[(col0 + c) * T_SEQ + t];
    }
    for (int i = tid; i < 10 * 64; i += NTHREADS) {
        int v = i >> 6, j = i & 63;
        const float* ev = emb + v * E_DIM;
        float4 r;
        float* rp = (float*)&r;
        #pragma unroll
        for (int q = 0; q < 4; q++) {
            const float* wx = WxTab[q] + (rank * 64 + j) * E_DIM;
            float s = 0.0f;
            #pragma unroll
            for (int e = 0; e < E_DIM; e++) s = fmaf(wx[e], ev[e], s);
            rp[q] = s;
        }
        pxt[i] = r;
    }
    if (tid == 0) {
        mbar_init(sb32 + OFF_MB,     MB_COUNT);
        mbar_init(sb32 + OFF_MB + 8, MB_COUNT);
    }

    // store targets: threadA -> {local STS, remote remA}; threadB -> {remB0, remB1}
    // signal target: threads 0-3 arrive at CTA (tid)'s mbar
    uint32_t remA, remB0, remB1, arrBase = 0;
    {
        uint32_t pr[CLUSTER];
        #pragma unroll
        for (int r = 0; r < CLUSTER; r++) pr[r] = mapa_rank(sb32, r);
        int rm[3], n = 0;
        #pragma unroll
        for (int r = 0; r < CLUSTER; r++) if (r != rank) rm[n++] = r;
        remA  = pr[rm[0]];
        remB0 = pr[rm[1]];
        remB1 = pr[rm[2]];
        if (tid < 4) arrBase = pr[tid] + OFF_MB;
    }

    __syncthreads();
    cluster_sync_();                 // mbar init + h0/B zero visible cluster-wide

    const uint32_t coff = (uint32_t)(g * SHI_W * 4);
    float cst = 0.0f;

    int p = 0;
    for (int t = 0; t < T_SEQ; t++) {
        const char* Bp = sb + OFF_BH + p * B_MAT;

        // ---- phase 1 (pre-wait): own 4 chunks (locally-written, sync'd by
        //      last iteration's __syncthreads) + preX lookup ----
        float h0[4] = {0,0,0,0}, h1[4] = {0,0,0,0};
        #pragma unroll
        for (int idx = 0; idx < 4; idx++) {
            const int kc = (4 * rank + idx) & 15;
            uint2 A = *(const uint2*)(Bp + coff + (uint32_t)(kc * 8 + tg * 2) * 4);
            mma16816h(h0, aHi[idx], A.x, A.y);
        }
        int xi = xbuf[t * G_COLS + cA];
        float4 px4 = pxt[xi * 64 + jloc];

        // ---- wait for peers' stores into buffer p (4 arrivals) ----
        if (t > 0)
            mbar_wait(sb32 + OFF_MB + p * 8, (uint32_t)(((t - 1) >> 1) & 1));

        // ---- phase 2: remaining 12 chunks, 2 chains ----
        #pragma unroll
        for (int idx = 4; idx < KC_N; idx++) {
            const int kc = (4 * rank + idx) & 15;
            uint2 A = *(const uint2*)(Bp + coff + (uint32_t)(kc * 8 + tg * 2) * 4);
            if (idx < 10) mma16816h(h0, aHi[idx], A.x, A.y);
            else          mma16816h(h1, aHi[idx], A.x, A.y);
        }
        float d0 = h0[0] + h1[0];    // (gate qa,   col 2tg)
        float d1 = h0[1] + h1[1];    // (gate qa,   col 2tg+1)
        float d2 = h0[2] + h1[2];    // (gate qa+2, col 2tg)
        float d3 = h0[3] + h1[3];    // (gate qa+2, col 2tg+1)

        // ---- gate exchange with lane^16 (same j, other gate-pair) ----
        float sA = qa ? d0 : d1;
        float rA = __shfl_xor_sync(0xffffffffu, sA, 16);
        float sB = qa ? d2 : d3;
        float rB = __shfl_xor_sync(0xffffffffu, sB, 16);
        float pg0 = (qa ? rA : d0) + biasA[0] + px4.x;   // gate g
        float pg1 = (qa ? d1 : rA) + biasA[1] + px4.y;   // gate i
        float pg2 = (qa ? rB : d2) + biasA[2] + px4.z;   // gate f
        float pg3 = (qa ? d3 : rB) + biasA[3] + px4.w;   // gate o

        // ---- activations + c/h update for (jloc, cA) ----
        float gg = tanhapx(pg0), ii = sigapx(pg1), ff = sigapx(pg2), oo = sigapx(pg3);
        cst = fmaf(gg, ii, cst * ff);
        const float hv = tanhapx(cst) * oo;

        // ---- j-pair exchange with lane^4: (even j, odd j) same col ----
        float ov = __shfl_xor_sync(0xffffffffu, hv, 4);
        float va = jlow ? hv : ov;    // k even
        float vb = jlow ? ov : hv;    // k odd
        const uint32_t pkt = pack_h2(va, vb);

        // ---- stores into buffer p^1: threadA = local STS + 1 remote;
        //      threadB = 2 remotes (partner holds identical pkt) ----
        const uint32_t dOff = (uint32_t)(OFF_BH + (p ^ 1) * B_MAT) + stCol;
        if (jlow) {
            *(uint32_t*)(sb + dOff) = pkt;          // own CTA, plain STS
            st_cluster_u32(remA + dOff, pkt);
        } else {
            st_cluster_u32(remB0 + dOff, pkt);
            st_cluster_u32(remB1 + dOff, pkt);
        }

        // ---- release: intra-CTA HB over all stores, then 4 cluster arrives ----
        __syncthreads();
        if (tid < 4)
            mbar_arrive_cluster(arrBase + (uint32_t)((p ^ 1) * 8));

        p ^= 1;
    }

    // drain: t=511 stores went into B[0]; its 256th completion ends phase 255 -> parity 1
    mbar_wait(sb32 + OFF_MB, 1u);

    // ---- projection: out[b, c] = sum_k Wp[c,k] h[k,b] + bp[c] (final h in B[0]) ----
    if (rank == 0 && tid < G_COLS * C_DIM) {
        const int col = tid / C_DIM;
        const int cls = tid % C_DIM;
        const uint32_t* Bc = (const uint32_t*)(sb + OFF_BH) + col * SHI_W;
        const float* wpr = Wp + cls * H_DIM;
        float s = bp[cls];
        for (int kp = 0; kp < H_DIM / 2; kp++) {
            uint32_t w = Bc[bw_kp(kp)];
            __half2 hw = *(__half2*)&w;
            s = fmaf(wpr[2 * kp],     __half2float(hw.x),
                fmaf(wpr[2 * kp + 1], __half2float(hw.y), s));
        }
        out[(col0 + col) * C_DIM + cls] = s;
    }
}

extern "C" void kernel_launch(void* const* d_in, const int* in_sizes, int n_in,
                              void* d_out, int out_size) {
    (void)in_sizes; (void)n_in; (void)out_size;
    const int*   x   = (const int*)  d_in[0];
    const float* emb = (const float*)d_in[1];
    const float* Wxg = (const float*)d_in[2];
    const float* Whg = (const float*)d_in[3];
    const float* bg  = (const float*)d_in[4];
    const float* Wxi = (const float*)d_in[5];
    const float* Whi = (const float*)d_in[6];
    const float* bi  = (const float*)d_in[7];
    const float* Wxf = (const float*)d_in[8];
    const float* Whf = (const float*)d_in[9];
    const float* bf  = (const float*)d_in[10];
    const float* Wxo = (const float*)d_in[11];
    const float* Who = (const float*)d_in[12];
    const float* bo  = (const float*)d_in[13];
    const float* Wp  = (const float*)d_in[14];
    const float* bp  = (const float*)d_in[15];
    float* out = (float*)d_out;

    cudaFuncSetAttribute(lstm_hmma_kernel,
                         cudaFuncAttributeMaxDynamicSharedMemorySize, SMEM_BYTES);
    // 32 clusters of 4 CTAs = 128 CTAs
    lstm_hmma_kernel<<<(B_DIM / G_COLS) * CLUSTER, NTHREADS, SMEM_BYTES>>>(
        x, emb, Wxg, Whg, bg, Wxi, Whi, bi, Wxf, Whf, bf, Wxo, Who, bo, Wp, bp, out);
}